// round 12
// baseline (speedup 1.0000x reference)
#include <cuda_runtime.h>
#include <cuda_bf16.h>
#include <cstdint>

#define B_    16
#define CIN   32
#define COUT  32
#define H_    256
#define W_    256
#define HW    (H_ * W_)

__device__ float g_bfinal[B_ * COUT];
// B fragments: [b][g=tap*2+ks (18)][fp (4)][lane (32)] uint4 = frag pair
__device__ uint4 g_bfrag4[B_ * 18 * 4 * 32];

// ---------------------------------------------------------------------------
// PTX helpers (generic, sm_80+)
// ---------------------------------------------------------------------------
__device__ __forceinline__ uint32_t smem_u32(const void* p) {
    uint32_t a;
    asm("{ .reg .u64 t; cvta.to.shared.u64 t, %1; cvt.u32.u64 %0, t; }"
        : "=r"(a) : "l"(p));
    return a;
}
__device__ __forceinline__ void ldsm4(uint32_t* r, uint32_t a) {
    asm volatile("ldmatrix.sync.aligned.m8n8.x4.shared.b16 {%0,%1,%2,%3}, [%4];"
                 : "=r"(r[0]), "=r"(r[1]), "=r"(r[2]), "=r"(r[3]) : "r"(a));
}
__device__ __forceinline__ void ldsm2(uint32_t* r, uint32_t a) {
    asm volatile("ldmatrix.sync.aligned.m8n8.x2.shared.b16 {%0,%1}, [%2];"
                 : "=r"(r[0]), "=r"(r[1]) : "r"(a));
}
__device__ __forceinline__ void mma16816(float* d, const uint32_t* a,
                                         uint32_t b0, uint32_t b1) {
    asm volatile(
        "mma.sync.aligned.m16n8k16.row.col.f32.bf16.bf16.f32 "
        "{%0,%1,%2,%3}, {%4,%5,%6,%7}, {%8,%9}, {%0,%1,%2,%3};"
        : "+f"(d[0]), "+f"(d[1]), "+f"(d[2]), "+f"(d[3])
        : "r"(a[0]), "r"(a[1]), "r"(a[2]), "r"(a[3]), "r"(b0), "r"(b1));
}
__device__ __forceinline__ uint32_t pack_bf2(__nv_bfloat16 a, __nv_bfloat16 b) {
    return (uint32_t)__bfloat16_as_ushort(a) |
           ((uint32_t)__bfloat16_as_ushort(b) << 16);
}

// ---------------------------------------------------------------------------
// Prep kernel: grid (9 taps, 16 batches), 128 thr.
// ---------------------------------------------------------------------------
__global__ void __launch_bounds__(128)
prep_kernel(const float* __restrict__ cond,
            const float* __restrict__ lpe,
            const float* __restrict__ wa_w,
            const float* __restrict__ wa_b,
            const float* __restrict__ ba_w,
            const float* __restrict__ ba_b,
            const float* __restrict__ bias,
            const float* __restrict__ weights) {
    __shared__ float ivec[512];
    __shared__ float wad[CIN];
    __shared__ char  smB[32 * 128];

    const int tid  = threadIdx.x;
    const int warp = tid >> 5;
    const int lane = tid & 31;
    const int kl   = blockIdx.x;
    const int b    = blockIdx.y;

#pragma unroll
    for (int k = 0; k < 4; k++) {
        int idx = tid + 128 * k;
        ivec[idx] = (idx < 256) ? cond[b * 256 + idx] : lpe[b * 256 + idx - 256];
    }
    __syncthreads();

    for (int d = warp; d < 32; d += 4) {
        const float* wr = wa_w + d * 512;
        float s = 0.f;
#pragma unroll
        for (int k = lane; k < 512; k += 32) s += ivec[k] * wr[k];
#pragma unroll
        for (int off = 16; off; off >>= 1) s += __shfl_xor_sync(0xffffffffu, s, off);
        if (lane == 0) wad[d] = s + wa_b[d];
    }
    if (kl == 0) {
        for (int d = warp; d < 32; d += 4) {
            const float* wr = ba_w + d * 512;
            float s = 0.f;
#pragma unroll
            for (int k = lane; k < 512; k += 32) s += ivec[k] * wr[k];
#pragma unroll
            for (int off = 16; off; off >>= 1) s += __shfl_xor_sync(0xffffffffu, s, off);
            if (lane == 0) g_bfinal[b * COUT + d] = bias[d] * (s + ba_b[d]);
        }
    }
    __syncthreads();

    for (int e = tid; e < 32 * 32; e += 128) {
        int ci = e >> 5;
        int o  = e & 31;
        float v = weights[(ci * 32 + o) * 9 + kl] * wad[ci];
        __nv_bfloat16 h = __float2bfloat16(v);
        __nv_bfloat16 l = __float2bfloat16(v - __bfloat162float(h));
        int ch = (ci >> 3) ^ (o & 7);
        int cl = (4 + (ci >> 3)) ^ (o & 7);
        int wb = (ci & 7) * 2;
        *(__nv_bfloat16*)(smB + o * 128 + ch * 16 + wb) = h;
        *(__nv_bfloat16*)(smB + o * 128 + cl * 16 + wb) = l;
    }
    __syncthreads();

    const uint32_t sbB = smem_u32(smB);
    uint2* dst = (uint2*)g_bfrag4;
    for (int s = warp; s < 16; s += 4) {
        int ks = s >> 3, hl = (s >> 2) & 1, nt = s & 3;
        int r  = nt * 8 + (lane & 7);
        int c0 = hl * 4 + ks * 2 + ((lane >> 3) & 1);
        uint32_t f[2];
        ldsm2(f, sbB + r * 128 + (uint32_t)((c0 ^ (r & 7)) << 4));
        int g    = kl * 2 + ks;
        int fidx = hl * 4 + nt;
        dst[((((size_t)b * 18 + g) * 4 + (fidx >> 1)) * 32 + lane) * 2 + (fidx & 1)] =
            make_uint2(f[0], f[1]);
    }
}

// ---------------------------------------------------------------------------
// Persistent warp-specialized conv.
// Grid = 152 CTAs (1/SM), 384 thr: warps 0-7 consumers (MMA), 8-11 producers.
// Tile = batch b, 8 output rows x 64 cols, all 32 Cout (2048 tiles).
// Double-buffered A tile: 660 pixel-rows x 128B each, hi/lo bf16, swizzled.
// Producers stage tile t+GRID into spare buffer while consumers MMA tile t.
// ---------------------------------------------------------------------------
#define APIX   660                 // 10 * 66
#define ABYTES (APIX * 128)        // 84480
#define SMEM_TOTAL (2 * ABYTES)    // 168960
#define NTHR 384
#define NCONS 256
#define GRID_P 152
#define NTILES 2048                // 4 x-tiles * 32 y-tiles * 16 batches

__device__ __forceinline__ void stage_tile(const float* __restrict__ x,
                                           char* __restrict__ buf,
                                           int t, int ptid) {
    const int bx = t & 3;
    const int by = (t >> 2) & 31;
    const int b  = t >> 7;
    const int gy0 = by * 8;
    const int gx0 = bx * 64;
    const float* xb = x + (size_t)b * CIN * HW;

    for (int p = ptid; p < APIX; p += 128) {
        const int iy = p / 66;
        const int ix = p - iy * 66;
        const int gy = gy0 - 1 + iy;
        const int gx = gx0 - 1 + ix;
        const bool ok = (unsigned)gy < (unsigned)H_ && (unsigned)gx < (unsigned)W_;
        const float* px = xb + (size_t)(ok ? gy * W_ + gx : 0);
        char* arow = buf + p * 128;
        const int psw = p & 7;
#pragma unroll
        for (int c = 0; c < 4; c++) {
            float v[8];
#pragma unroll
            for (int j = 0; j < 8; j++)
                v[j] = ok ? px[(size_t)(8 * c + j) * HW] : 0.f;
            __nv_bfloat16 h[8];
            uint4 hv, lv;
#pragma unroll
            for (int j = 0; j < 8; j++) h[j] = __float2bfloat16(v[j]);
            hv.x = pack_bf2(h[0], h[1]);
            hv.y = pack_bf2(h[2], h[3]);
            hv.z = pack_bf2(h[4], h[5]);
            hv.w = pack_bf2(h[6], h[7]);
            __nv_bfloat16 l[8];
#pragma unroll
            for (int j = 0; j < 8; j++)
                l[j] = __float2bfloat16(v[j] - __bfloat162float(h[j]));
            lv.x = pack_bf2(l[0], l[1]);
            lv.y = pack_bf2(l[2], l[3]);
            lv.z = pack_bf2(l[4], l[5]);
            lv.w = pack_bf2(l[6], l[7]);
            *(uint4*)(arow + ((c ^ psw) << 4))       = hv;
            *(uint4*)(arow + (((c + 4) ^ psw) << 4)) = lv;
        }
    }
}

__device__ __forceinline__ void compute_tile(char* __restrict__ buf,
                                             float* __restrict__ out,
                                             int t, int warp, int lane) {
    const int bx = t & 3;
    const int by = (t >> 2) & 31;
    const int b  = t >> 7;
    const int gy0 = by * 8;
    const int gx0 = bx * 64;

    // Per-tile bias values for this lane's 8 distinct o indices
    float bf_[8];
#pragma unroll
    for (int nt = 0; nt < 4; nt++)
#pragma unroll
        for (int jj = 0; jj < 2; jj++)
            bf_[nt * 2 + jj] = g_bfinal[b * 32 + nt * 8 + (lane & 3) * 2 + jj];

    const uint32_t sbA = smem_u32(buf);
    const int kh = lane >> 4;
    const uint4* __restrict__ bfb = g_bfrag4 + (size_t)b * 18 * 4 * 32 + lane;
    const int pbase = warp * 66 + (lane & 15);

    float acc[4][4][4];
#pragma unroll
    for (int mt = 0; mt < 4; mt++)
#pragma unroll
        for (int nt = 0; nt < 4; nt++)
#pragma unroll
            for (int j = 0; j < 4; j++) acc[mt][nt][j] = 0.f;

#pragma unroll
    for (int tap = 0; tap < 9; tap++) {
        const int pshift = (tap / 3) * 66 + (tap % 3);
#pragma unroll
        for (int ks = 0; ks < 2; ks++) {
            const uint4* bp = bfb + (size_t)(tap * 2 + ks) * 4 * 32;
            uint4 q0 = bp[0 * 32];
            uint4 q1 = bp[1 * 32];
            uint4 q2 = bp[2 * 32];
            uint4 q3 = bp[3 * 32];

#pragma unroll
            for (int mt = 0; mt < 4; mt++) {
                const int pa = pbase + mt * 16 + pshift;
                const uint32_t arow = sbA + pa * 128;
                const int     psw  = pa & 7;
                uint32_t ah[4], al[4];
                ldsm4(ah, arow + (uint32_t)(((ks * 2 + kh)     ^ psw) << 4));
                ldsm4(al, arow + (uint32_t)(((4 + ks * 2 + kh) ^ psw) << 4));

                float* a0 = acc[mt][0];
                float* a1 = acc[mt][1];
                float* a2 = acc[mt][2];
                float* a3 = acc[mt][3];
                mma16816(a0, ah, q0.x, q0.y);
                mma16816(a0, al, q0.x, q0.y);
                mma16816(a0, ah, q2.x, q2.y);
                mma16816(a1, ah, q0.z, q0.w);
                mma16816(a1, al, q0.z, q0.w);
                mma16816(a1, ah, q2.z, q2.w);
                mma16816(a2, ah, q1.x, q1.y);
                mma16816(a2, al, q1.x, q1.y);
                mma16816(a2, ah, q3.x, q3.y);
                mma16816(a3, ah, q1.z, q1.w);
                mma16816(a3, al, q1.z, q1.w);
                mma16816(a3, ah, q3.z, q3.w);
            }
        }
    }

    // Consumers-only barrier: all consumer ldsm reads done before scratch
    asm volatile("bar.sync 1, %0;" :: "n"(NCONS) : "memory");

    float* scratch = (float*)buf + warp * 2048;   // 8KB per warp
#pragma unroll
    for (int mt = 0; mt < 4; mt++) {
#pragma unroll
        for (int nt = 0; nt < 4; nt++) {
#pragma unroll
            for (int j = 0; j < 4; j++) {
                int o   = nt * 8 + (lane & 3) * 2 + (j & 1);
                int pix = mt * 16 + (j >> 1) * 8 + (lane >> 2);
                scratch[o * 64 + pix] = acc[mt][nt][j] + bf_[nt * 2 + (j & 1)];
            }
        }
    }
    __syncwarp();

    const int gy = gy0 + warp;
    float* ob = out + (size_t)b * COUT * HW + (size_t)gy * W_ + gx0;
#pragma unroll
    for (int k = 0; k < 16; k++) {
        int o  = 2 * k + (lane >> 4);
        int xl = (lane & 15) * 4;
        float4 v = *(float4*)&scratch[o * 64 + xl];
        *(float4*)(ob + (size_t)o * HW + xl) = v;
    }
}

__global__ void __launch_bounds__(NTHR, 1)
conv_mma(const float* __restrict__ x,
         float* __restrict__ out) {
    extern __shared__ __align__(128) char smem[];
    const int tid  = threadIdx.x;
    const int warp = tid >> 5;
    const int lane = tid & 31;
    const bool producer = warp >= 8;

    // Prologue: stage first tile into buffer 0
    if (producer) stage_tile(x, smem, blockIdx.x, tid & 127);

    int i = 0;
    for (int t = blockIdx.x; t < NTILES; t += GRID_P, i ^= 1) {
        __syncthreads();   // buf[i] full; previous consumer phase complete
        if (producer) {
            int tn = t + GRID_P;
            if (tn < NTILES)
                stage_tile(x, smem + (i ^ 1) * ABYTES, tn, tid & 127);
        } else {
            compute_tile(smem + i * ABYTES, out, t, warp, lane);
        }
    }
}

// ---------------------------------------------------------------------------
extern "C" void kernel_launch(void* const* d_in, const int* in_sizes, int n_in,
                              void* d_out, int out_size) {
    const float* x    = (const float*)d_in[0];
    const float* cond = (const float*)d_in[1];
    const float* lpe  = (const float*)d_in[2];
    const float* w    = (const float*)d_in[3];
    const float* bias = (const float*)d_in[4];
    const float* wa_w = (const float*)d_in[5];
    const float* wa_b = (const float*)d_in[6];
    const float* ba_w = (const float*)d_in[7];
    const float* ba_b = (const float*)d_in[8];
    float* out = (float*)d_out;

    cudaFuncSetAttribute(conv_mma,
                         cudaFuncAttributeMaxDynamicSharedMemorySize, SMEM_TOTAL);

    prep_kernel<<<dim3(9, B_), 128>>>(cond, lpe, wa_w, wa_b, ba_w, ba_b, bias, w);

    conv_mma<<<GRID_P, NTHR, SMEM_TOTAL>>>(x, out);
}

// round 13
// speedup vs baseline: 1.2570x; 1.2570x over previous
#include <cuda_runtime.h>
#include <cuda_fp16.h>
#include <cstdint>

#define B_    16
#define CIN   32
#define COUT  32
#define H_    256
#define W_    256
#define HW    (H_ * W_)

__device__ float g_bfinal[B_ * COUT];
// B fragments (single fp16): [b][g=tap*2+ks (18)][fp (2)][lane (32)] uint4 =
// frag pair (fp = nt>>1; .xy = even nt, .zw = odd nt)
__device__ uint4 g_bfrag2[B_ * 18 * 2 * 32];

// ---------------------------------------------------------------------------
// PTX helpers (generic, sm_80+)
// ---------------------------------------------------------------------------
__device__ __forceinline__ uint32_t smem_u32(const void* p) {
    uint32_t a;
    asm("{ .reg .u64 t; cvta.to.shared.u64 t, %1; cvt.u32.u64 %0, t; }"
        : "=r"(a) : "l"(p));
    return a;
}
__device__ __forceinline__ void ldsm4(uint32_t* r, uint32_t a) {
    asm volatile("ldmatrix.sync.aligned.m8n8.x4.shared.b16 {%0,%1,%2,%3}, [%4];"
                 : "=r"(r[0]), "=r"(r[1]), "=r"(r[2]), "=r"(r[3]) : "r"(a));
}
__device__ __forceinline__ void ldsm2(uint32_t* r, uint32_t a) {
    asm volatile("ldmatrix.sync.aligned.m8n8.x2.shared.b16 {%0,%1}, [%2];"
                 : "=r"(r[0]), "=r"(r[1]) : "r"(a));
}
__device__ __forceinline__ void mma16816(float* d, const uint32_t* a,
                                         uint32_t b0, uint32_t b1) {
    asm volatile(
        "mma.sync.aligned.m16n8k16.row.col.f32.f16.f16.f32 "
        "{%0,%1,%2,%3}, {%4,%5,%6,%7}, {%8,%9}, {%0,%1,%2,%3};"
        : "+f"(d[0]), "+f"(d[1]), "+f"(d[2]), "+f"(d[3])
        : "r"(a[0]), "r"(a[1]), "r"(a[2]), "r"(a[3]), "r"(b0), "r"(b1));
}
__device__ __forceinline__ uint32_t pack_h2(__half a, __half b) {
    return (uint32_t)__half_as_ushort(a) |
           ((uint32_t)__half_as_ushort(b) << 16);
}

// ---------------------------------------------------------------------------
// Prep kernel: grid (9 taps, 16 batches), 128 thr. Scaled weights -> single
// fp16 -> swizzled smem -> ldsm2-exact fragments.
// ---------------------------------------------------------------------------
__global__ void __launch_bounds__(128)
prep_kernel(const float* __restrict__ cond,
            const float* __restrict__ lpe,
            const float* __restrict__ wa_w,
            const float* __restrict__ wa_b,
            const float* __restrict__ ba_w,
            const float* __restrict__ ba_b,
            const float* __restrict__ bias,
            const float* __restrict__ weights) {
    __shared__ float ivec[512];
    __shared__ float wad[CIN];
    __shared__ char  smB[32 * 128];

    const int tid  = threadIdx.x;
    const int warp = tid >> 5;
    const int lane = tid & 31;
    const int kl   = blockIdx.x;
    const int b    = blockIdx.y;

#pragma unroll
    for (int k = 0; k < 4; k++) {
        int idx = tid + 128 * k;
        ivec[idx] = (idx < 256) ? cond[b * 256 + idx] : lpe[b * 256 + idx - 256];
    }
    __syncthreads();

    for (int d = warp; d < 32; d += 4) {
        const float* wr = wa_w + d * 512;
        float s = 0.f;
#pragma unroll
        for (int k = lane; k < 512; k += 32) s += ivec[k] * wr[k];
#pragma unroll
        for (int off = 16; off; off >>= 1) s += __shfl_xor_sync(0xffffffffu, s, off);
        if (lane == 0) wad[d] = s + wa_b[d];
    }
    if (kl == 0) {
        for (int d = warp; d < 32; d += 4) {
            const float* wr = ba_w + d * 512;
            float s = 0.f;
#pragma unroll
            for (int k = lane; k < 512; k += 32) s += ivec[k] * wr[k];
#pragma unroll
            for (int off = 16; off; off >>= 1) s += __shfl_xor_sync(0xffffffffu, s, off);
            if (lane == 0) g_bfinal[b * COUT + d] = bias[d] * (s + ba_b[d]);
        }
    }
    __syncthreads();

    // Build this tap's 32-row B slice: scaled, single fp16, hi chunks only
    for (int e = tid; e < 32 * 32; e += 128) {
        int ci = e >> 5;
        int o  = e & 31;
        float v = weights[(ci * 32 + o) * 9 + kl] * wad[ci];
        int ch = (ci >> 3) ^ (o & 7);
        int wb = (ci & 7) * 2;
        *(__half*)(smB + o * 128 + ch * 16 + wb) = __float2half(v);
    }
    __syncthreads();

    // Emit fragments: 8 (ks,nt) combos for this tap
    const uint32_t sbB = smem_u32(smB);
    uint2* dst = (uint2*)g_bfrag2;
    for (int s = warp; s < 8; s += 4) {
        int ks = s >> 2, nt = s & 3;
        int r  = nt * 8 + (lane & 7);
        int c0 = ks * 2 + ((lane >> 3) & 1);
        uint32_t f[2];
        ldsm2(f, sbB + r * 128 + (uint32_t)((c0 ^ (r & 7)) << 4));
        int g = kl * 2 + ks;
        dst[((((size_t)b * 18 + g) * 2 + (nt >> 1)) * 32 + lane) * 2 + (nt & 1)] =
            make_uint2(f[0], f[1]);
    }
}

// ---------------------------------------------------------------------------
// Conv mainloop (R11 architecture). CTA = batch b, 8 rows x 64 cols, all 32
// Cout; 256 thr = 8 warps; warp w owns row w (4 m-tiles); 2 CTAs/SM.
// A smem: 660 pixel-rows x 128B [32 fp16 hi | 32 fp16 lo], swizzled.
// D = Ah*B + Al*B (B single fp16): 8 MMAs per (tap,ks,mt).
// ---------------------------------------------------------------------------
#define APIX   660                 // 10 * 66
#define ABYTES (APIX * 128)        // 84480
#define NTHR 256

__global__ void __launch_bounds__(NTHR, 2)
conv_mma(const float* __restrict__ x,
         float* __restrict__ out) {
    extern __shared__ __align__(128) char smA[];
    __shared__ float bfc[COUT];

    const int tid  = threadIdx.x;
    const int warp = tid >> 5;
    const int lane = tid & 31;
    const int b    = blockIdx.z;
    const int gy0  = blockIdx.y * 8;
    const int gx0  = blockIdx.x * 64;

    if (tid < COUT) bfc[tid] = g_bfinal[b * COUT + tid];

    // ---- Stage A: per pixel-row, 4 ci-octets -> 2x STS.128 (hi, lo) ----
    const float* xb = x + (size_t)b * CIN * HW;
    for (int p = tid; p < APIX; p += NTHR) {
        const int iy = p / 66;
        const int ix = p - iy * 66;
        const int gy = gy0 - 1 + iy;
        const int gx = gx0 - 1 + ix;
        const bool ok = (unsigned)gy < (unsigned)H_ && (unsigned)gx < (unsigned)W_;
        const float* px = xb + (size_t)(ok ? gy * W_ + gx : 0);
        char* arow = smA + p * 128;
        const int psw = p & 7;
#pragma unroll
        for (int c = 0; c < 4; c++) {
            float v[8];
#pragma unroll
            for (int j = 0; j < 8; j++)
                v[j] = ok ? px[(size_t)(8 * c + j) * HW] : 0.f;
            __half h[8];
            uint4 hv, lv;
#pragma unroll
            for (int j = 0; j < 8; j++) h[j] = __float2half(v[j]);
            hv.x = pack_h2(h[0], h[1]);
            hv.y = pack_h2(h[2], h[3]);
            hv.z = pack_h2(h[4], h[5]);
            hv.w = pack_h2(h[6], h[7]);
            __half l[8];
#pragma unroll
            for (int j = 0; j < 8; j++)
                l[j] = __float2half(v[j] - __half2float(h[j]));
            lv.x = pack_h2(l[0], l[1]);
            lv.y = pack_h2(l[2], l[3]);
            lv.z = pack_h2(l[4], l[5]);
            lv.w = pack_h2(l[6], l[7]);
            *(uint4*)(arow + ((c ^ psw) << 4))       = hv;
            *(uint4*)(arow + (((c + 4) ^ psw) << 4)) = lv;
        }
    }
    __syncthreads();

    // ---- MMA mainloop: 4 m-tiles share every B-fragment load ----
    const uint32_t sbA = smem_u32(smA);
    const int kh = lane >> 4;
    const uint4* __restrict__ bfb = g_bfrag2 + (size_t)b * 18 * 2 * 32 + lane;
    const int pbase = warp * 66 + (lane & 15);

    float acc[4][4][4];
#pragma unroll
    for (int mt = 0; mt < 4; mt++)
#pragma unroll
        for (int nt = 0; nt < 4; nt++)
#pragma unroll
            for (int j = 0; j < 4; j++) acc[mt][nt][j] = 0.f;

#pragma unroll
    for (int tap = 0; tap < 9; tap++) {
        const int pshift = (tap / 3) * 66 + (tap % 3);
#pragma unroll
        for (int ks = 0; ks < 2; ks++) {
            const uint4* bp = bfb + (size_t)(tap * 2 + ks) * 2 * 32;
            uint4 q0 = bp[0 * 32];     // nt0 (.xy), nt1 (.zw)
            uint4 q1 = bp[1 * 32];     // nt2 (.xy), nt3 (.zw)

#pragma unroll
            for (int mt = 0; mt < 4; mt++) {
                const int pa = pbase + mt * 16 + pshift;
                const uint32_t arow = sbA + pa * 128;
                const int     psw  = pa & 7;
                uint32_t ah[4], al[4];
                ldsm4(ah, arow + (uint32_t)(((ks * 2 + kh)     ^ psw) << 4));
                ldsm4(al, arow + (uint32_t)(((4 + ks * 2 + kh) ^ psw) << 4));

                float* a0 = acc[mt][0];
                float* a1 = acc[mt][1];
                float* a2 = acc[mt][2];
                float* a3 = acc[mt][3];
                mma16816(a0, ah, q0.x, q0.y);
                mma16816(a0, al, q0.x, q0.y);
                mma16816(a1, ah, q0.z, q0.w);
                mma16816(a1, al, q0.z, q0.w);
                mma16816(a2, ah, q1.x, q1.y);
                mma16816(a2, al, q1.x, q1.y);
                mma16816(a3, ah, q1.z, q1.w);
                mma16816(a3, al, q1.z, q1.w);
            }
        }
    }

    // ---- Epilogue: warp-private smem transpose -> coalesced STG.128 ----
    __syncthreads();   // all warps done reading A tile
    float* scratch = (float*)smA + warp * 2048;   // 8KB per warp

#pragma unroll
    for (int mt = 0; mt < 4; mt++) {
#pragma unroll
        for (int nt = 0; nt < 4; nt++) {
#pragma unroll
            for (int j = 0; j < 4; j++) {
                int o   = nt * 8 + (lane & 3) * 2 + (j & 1);
                int pix = mt * 16 + (j >> 1) * 8 + (lane >> 2);
                scratch[o * 64 + pix] = acc[mt][nt][j] + bfc[o];
            }
        }
    }
    __syncwarp();

    const int gy = gy0 + warp;
    float* ob = out + (size_t)b * COUT * HW + (size_t)gy * W_ + gx0;
#pragma unroll
    for (int k = 0; k < 16; k++) {
        int o  = 2 * k + (lane >> 4);
        int xl = (lane & 15) * 4;
        float4 v = *(float4*)&scratch[o * 64 + xl];
        *(float4*)(ob + (size_t)o * HW + xl) = v;
    }
}

// ---------------------------------------------------------------------------
extern "C" void kernel_launch(void* const* d_in, const int* in_sizes, int n_in,
                              void* d_out, int out_size) {
    const float* x    = (const float*)d_in[0];
    const float* cond = (const float*)d_in[1];
    const float* lpe  = (const float*)d_in[2];
    const float* w    = (const float*)d_in[3];
    const float* bias = (const float*)d_in[4];
    const float* wa_w = (const float*)d_in[5];
    const float* wa_b = (const float*)d_in[6];
    const float* ba_w = (const float*)d_in[7];
    const float* ba_b = (const float*)d_in[8];
    float* out = (float*)d_out;

    cudaFuncSetAttribute(conv_mma,
                         cudaFuncAttributeMaxDynamicSharedMemorySize, ABYTES);

    prep_kernel<<<dim3(9, B_), 128>>>(cond, lpe, wa_w, wa_b, ba_w, ba_b, bias, w);

    dim3 grid(W_ / 64, H_ / 8, B_);
    conv_mma<<<grid, NTHR, ABYTES>>>(x, out);
}

// round 14
// speedup vs baseline: 1.5453x; 1.2293x over previous
#include <cuda_runtime.h>
#include <cuda_fp16.h>
#include <cstdint>

#define B_    16
#define CIN   32
#define COUT  32
#define H_    256
#define W_    256
#define HW    (H_ * W_)

__device__ float g_bfinal[B_ * COUT];
// B fragments (single fp16): [b][g=tap*2+ks (18)][fp (2)][lane (32)] uint4 =
// frag pair (fp = nt>>1; .xy = even nt, .zw = odd nt)
__device__ uint4 g_bfrag2[B_ * 18 * 2 * 32];

// ---------------------------------------------------------------------------
// PTX helpers (generic, sm_80+)
// ---------------------------------------------------------------------------
__device__ __forceinline__ uint32_t smem_u32(const void* p) {
    uint32_t a;
    asm("{ .reg .u64 t; cvta.to.shared.u64 t, %1; cvt.u32.u64 %0, t; }"
        : "=r"(a) : "l"(p));
    return a;
}
__device__ __forceinline__ void ldsm4(uint32_t* r, uint32_t a) {
    asm volatile("ldmatrix.sync.aligned.m8n8.x4.shared.b16 {%0,%1,%2,%3}, [%4];"
                 : "=r"(r[0]), "=r"(r[1]), "=r"(r[2]), "=r"(r[3]) : "r"(a));
}
__device__ __forceinline__ void ldsm2(uint32_t* r, uint32_t a) {
    asm volatile("ldmatrix.sync.aligned.m8n8.x2.shared.b16 {%0,%1}, [%2];"
                 : "=r"(r[0]), "=r"(r[1]) : "r"(a));
}
__device__ __forceinline__ void mma16816(float* d, const uint32_t* a,
                                         uint32_t b0, uint32_t b1) {
    asm volatile(
        "mma.sync.aligned.m16n8k16.row.col.f32.f16.f16.f32 "
        "{%0,%1,%2,%3}, {%4,%5,%6,%7}, {%8,%9}, {%0,%1,%2,%3};"
        : "+f"(d[0]), "+f"(d[1]), "+f"(d[2]), "+f"(d[3])
        : "r"(a[0]), "r"(a[1]), "r"(a[2]), "r"(a[3]), "r"(b0), "r"(b1));
}
__device__ __forceinline__ uint32_t pack_h2(__half a, __half b) {
    return (uint32_t)__half_as_ushort(a) |
           ((uint32_t)__half_as_ushort(b) << 16);
}

// ---------------------------------------------------------------------------
// Prep kernel: grid (9 taps, 16 batches), 128 thr. Scaled weights -> single
// fp16 -> swizzled smem -> ldsm2-exact fragments.
// ---------------------------------------------------------------------------
__global__ void __launch_bounds__(128)
prep_kernel(const float* __restrict__ cond,
            const float* __restrict__ lpe,
            const float* __restrict__ wa_w,
            const float* __restrict__ wa_b,
            const float* __restrict__ ba_w,
            const float* __restrict__ ba_b,
            const float* __restrict__ bias,
            const float* __restrict__ weights) {
    __shared__ float ivec[512];
    __shared__ float wad[CIN];
    __shared__ char  smB[32 * 128];

    const int tid  = threadIdx.x;
    const int warp = tid >> 5;
    const int lane = tid & 31;
    const int kl   = blockIdx.x;
    const int b    = blockIdx.y;

#pragma unroll
    for (int k = 0; k < 4; k++) {
        int idx = tid + 128 * k;
        ivec[idx] = (idx < 256) ? cond[b * 256 + idx] : lpe[b * 256 + idx - 256];
    }
    __syncthreads();

    for (int d = warp; d < 32; d += 4) {
        const float* wr = wa_w + d * 512;
        float s = 0.f;
#pragma unroll
        for (int k = lane; k < 512; k += 32) s += ivec[k] * wr[k];
#pragma unroll
        for (int off = 16; off; off >>= 1) s += __shfl_xor_sync(0xffffffffu, s, off);
        if (lane == 0) wad[d] = s + wa_b[d];
    }
    if (kl == 0) {
        for (int d = warp; d < 32; d += 4) {
            const float* wr = ba_w + d * 512;
            float s = 0.f;
#pragma unroll
            for (int k = lane; k < 512; k += 32) s += ivec[k] * wr[k];
#pragma unroll
            for (int off = 16; off; off >>= 1) s += __shfl_xor_sync(0xffffffffu, s, off);
            if (lane == 0) g_bfinal[b * COUT + d] = bias[d] * (s + ba_b[d]);
        }
    }
    __syncthreads();

    // Build this tap's 32-row B slice: scaled, single fp16
    for (int e = tid; e < 32 * 32; e += 128) {
        int ci = e >> 5;
        int o  = e & 31;
        float v = weights[(ci * 32 + o) * 9 + kl] * wad[ci];
        int ch = (ci >> 3) ^ (o & 7);
        int wb = (ci & 7) * 2;
        *(__half*)(smB + o * 128 + ch * 16 + wb) = __float2half(v);
    }
    __syncthreads();

    // Emit fragments: 8 (ks,nt) combos for this tap
    const uint32_t sbB = smem_u32(smB);
    uint2* dst = (uint2*)g_bfrag2;
    for (int s = warp; s < 8; s += 4) {
        int ks = s >> 2, nt = s & 3;
        int r  = nt * 8 + (lane & 7);
        int c0 = ks * 2 + ((lane >> 3) & 1);
        uint32_t f[2];
        ldsm2(f, sbB + r * 128 + (uint32_t)((c0 ^ (r & 7)) << 4));
        int g = kl * 2 + ks;
        dst[((((size_t)b * 18 + g) * 2 + (nt >> 1)) * 32 + lane) * 2 + (nt & 1)] =
            make_uint2(f[0], f[1]);
    }
}

// ---------------------------------------------------------------------------
// Conv mainloop. CTA = batch b, 8 rows x 64 cols, all 32 Cout; 256 thr =
// 8 warps; warp w owns row w (4 m-tiles); 2 CTAs/SM.
// A smem: 660 pixel-rows x 128B, chunks 0-3 = 32 fp16 (single precision
// product), chunks 4-7 unused; 16B chunks XOR-swizzled by (p&7).
// D = A*B single fp16 product: 4 MMAs per (tap,ks,mt).
// ---------------------------------------------------------------------------
#define APIX   660                 // 10 * 66
#define ABYTES (APIX * 128)        // 84480
#define NTHR 256

__global__ void __launch_bounds__(NTHR, 2)
conv_mma(const float* __restrict__ x,
         float* __restrict__ out) {
    extern __shared__ __align__(128) char smA[];
    __shared__ float bfc[COUT];

    const int tid  = threadIdx.x;
    const int warp = tid >> 5;
    const int lane = tid & 31;
    const int b    = blockIdx.z;
    const int gy0  = blockIdx.y * 8;
    const int gx0  = blockIdx.x * 64;

    if (tid < COUT) bfc[tid] = g_bfinal[b * COUT + tid];

    // ---- Stage A: per pixel-row, 4 ci-octets -> 1x STS.128 each ----
    const float* xb = x + (size_t)b * CIN * HW;
    for (int p = tid; p < APIX; p += NTHR) {
        const int iy = p / 66;
        const int ix = p - iy * 66;
        const int gy = gy0 - 1 + iy;
        const int gx = gx0 - 1 + ix;
        const bool ok = (unsigned)gy < (unsigned)H_ && (unsigned)gx < (unsigned)W_;
        const float* px = xb + (size_t)(ok ? gy * W_ + gx : 0);
        char* arow = smA + p * 128;
        const int psw = p & 7;
#pragma unroll
        for (int c = 0; c < 4; c++) {
            float v[8];
#pragma unroll
            for (int j = 0; j < 8; j++)
                v[j] = ok ? px[(size_t)(8 * c + j) * HW] : 0.f;
            __half h[8];
#pragma unroll
            for (int j = 0; j < 8; j++) h[j] = __float2half(v[j]);
            uint4 hv;
            hv.x = pack_h2(h[0], h[1]);
            hv.y = pack_h2(h[2], h[3]);
            hv.z = pack_h2(h[4], h[5]);
            hv.w = pack_h2(h[6], h[7]);
            *(uint4*)(arow + ((c ^ psw) << 4)) = hv;
        }
    }
    __syncthreads();

    // ---- MMA mainloop: 4 m-tiles share every B-fragment load ----
    const uint32_t sbA = smem_u32(smA);
    const int kh = lane >> 4;
    const uint4* __restrict__ bfb = g_bfrag2 + (size_t)b * 18 * 2 * 32 + lane;
    const int pbase = warp * 66 + (lane & 15);

    float acc[4][4][4];
#pragma unroll
    for (int mt = 0; mt < 4; mt++)
#pragma unroll
        for (int nt = 0; nt < 4; nt++)
#pragma unroll
            for (int j = 0; j < 4; j++) acc[mt][nt][j] = 0.f;

#pragma unroll
    for (int tap = 0; tap < 9; tap++) {
        const int pshift = (tap / 3) * 66 + (tap % 3);
#pragma unroll
        for (int ks = 0; ks < 2; ks++) {
            const uint4* bp = bfb + (size_t)(tap * 2 + ks) * 2 * 32;
            uint4 q0 = bp[0 * 32];     // nt0 (.xy), nt1 (.zw)
            uint4 q1 = bp[1 * 32];     // nt2 (.xy), nt3 (.zw)

#pragma unroll
            for (int mt = 0; mt < 4; mt++) {
                const int pa = pbase + mt * 16 + pshift;
                const uint32_t arow = sbA + pa * 128;
                const int     psw  = pa & 7;
                uint32_t ah[4];
                ldsm4(ah, arow + (uint32_t)(((ks * 2 + kh) ^ psw) << 4));

                mma16816(acc[mt][0], ah, q0.x, q0.y);
                mma16816(acc[mt][1], ah, q0.z, q0.w);
                mma16816(acc[mt][2], ah, q1.x, q1.y);
                mma16816(acc[mt][3], ah, q1.z, q1.w);
            }
        }
    }

    // ---- Epilogue: warp-private smem transpose -> coalesced STG.128 ----
    __syncthreads();   // all warps done reading A tile
    float* scratch = (float*)smA + warp * 2048;   // 8KB per warp

#pragma unroll
    for (int mt = 0; mt < 4; mt++) {
#pragma unroll
        for (int nt = 0; nt < 4; nt++) {
#pragma unroll
            for (int j = 0; j < 4; j++) {
                int o   = nt * 8 + (lane & 3) * 2 + (j & 1);
                int pix = mt * 16 + (j >> 1) * 8 + (lane >> 2);
                scratch[o * 64 + pix] = acc[mt][nt][j] + bfc[o];
            }
        }
    }
    __syncwarp();

    const int gy = gy0 + warp;
    float* ob = out + (size_t)b * COUT * HW + (size_t)gy * W_ + gx0;
#pragma unroll
    for (int k = 0; k < 16; k++) {
        int o  = 2 * k + (lane >> 4);
        int xl = (lane & 15) * 4;
        float4 v = *(float4*)&scratch[o * 64 + xl];
        *(float4*)(ob + (size_t)o * HW + xl) = v;
    }
}

// ---------------------------------------------------------------------------
extern "C" void kernel_launch(void* const* d_in, const int* in_sizes, int n_in,
                              void* d_out, int out_size) {
    const float* x    = (const float*)d_in[0];
    const float* cond = (const float*)d_in[1];
    const float* lpe  = (const float*)d_in[2];
    const float* w    = (const float*)d_in[3];
    const float* bias = (const float*)d_in[4];
    const float* wa_w = (const float*)d_in[5];
    const float* wa_b = (const float*)d_in[6];
    const float* ba_w = (const float*)d_in[7];
    const float* ba_b = (const float*)d_in[8];
    float* out = (float*)d_out;

    cudaFuncSetAttribute(conv_mma,
                         cudaFuncAttributeMaxDynamicSharedMemorySize, ABYTES);

    prep_kernel<<<dim3(9, B_), 128>>>(cond, lpe, wa_w, wa_b, ba_w, ba_b, bias, w);

    dim3 grid(W_ / 64, H_ / 8, B_);
    conv_mma<<<grid, NTHR, ABYTES>>>(x, out);
}